// round 16
// baseline (speedup 1.0000x reference)
#include <cuda_runtime.h>
#include <cuda.h>
#include <math.h>
#include <stdint.h>

#define NE   8
#define HD   2048
#define ID   1024
#define TMAX 8192
#define RMAX (2*TMAX)

#define KC      32                    // K fp32 elems per chunk (128 bytes/row)
#define NST     3
#define A_ROWS  128
#define A_TILE  (A_ROWS*128)          // 16384 bytes
#define STG_B   (2*A_TILE)            // 32768 (A + B)
#define STG_TX  32768
#define DSMEM   (NST*STG_B + 1024)    // 99328 -> 2 CTAs/SM

// ---------------- persistent device scratch ----------------
__device__ int   g_cnt[NE];
__device__ int   g_off[NE + 1];
__device__ float g_wt[NE][TMAX];
__device__ int4  g_slot[TMAX];
__device__ __align__(256) float g_xg[(size_t)RMAX * HD];   // gathered tf32 x (slot order)
__device__ __align__(256) float g_hr[(size_t)RMAX * ID];   // GLU out (tf32-rounded)
__device__ __align__(256) float g_fc[(size_t)RMAX * 2048]; // proj out

// ---------------- PTX helpers ----------------
__device__ __forceinline__ uint32_t smem_u32(const void* p) {
    uint32_t a;
    asm("{ .reg .u64 t; cvta.to.shared.u64 t, %1; cvt.u32.u64 %0, t; }" : "=r"(a) : "l"(p));
    return a;
}
__device__ __forceinline__ void tma2d(uint32_t dst, const CUtensorMap* tm,
                                      int cx, int cy, uint32_t mbar) {
    asm volatile(
        "cp.async.bulk.tensor.2d.shared::cta.global.tile.mbarrier::complete_tx::bytes "
        "[%0], [%1, {%2, %3}], [%4];"
        :: "r"(dst), "l"(tm), "r"(cx), "r"(cy), "r"(mbar) : "memory");
}
#define MBARRIER_INIT(mbar, cnt) \
    asm volatile("mbarrier.init.shared.b64 [%0], %1;" :: "r"((uint32_t)(mbar)), "r"((uint32_t)(cnt)) : "memory")
#define MBARRIER_EXPECT_TX(mbar, tx) \
    asm volatile("mbarrier.arrive.expect_tx.shared.b64 _, [%0], %1;" :: "r"((uint32_t)(mbar)), "r"((uint32_t)(tx)) : "memory")
#define FENCE_PROXY() asm volatile("fence.proxy.async.shared::cta;" ::: "memory")
#define BAR_SYNC(id)   asm volatile("bar.sync %0, 256;"   :: "r"(id) : "memory")
#define BAR_ARRIVE(id) asm volatile("bar.arrive %0, 256;" :: "r"(id) : "memory")

#define MBARRIER_WAIT_PARITY(mbar_addr, phase_parity) do {                                   \
    uint32_t _mbar = (uint32_t)(mbar_addr);                                                  \
    uint32_t _parity = (uint32_t)(phase_parity);                                             \
    uint32_t _done;                                                                          \
    asm volatile("{\n\t.reg .pred p;\n\t"                                                    \
        "mbarrier.try_wait.parity.acquire.cta.shared::cta.b64 p, [%1], %2;\n\t"              \
        "selp.b32 %0, 1, 0, p;\n\t}"                                                         \
        : "=r"(_done) : "r"(_mbar), "r"(_parity) : "memory");                                \
    if (!_done) {                                                                            \
        asm volatile("{\n\t.reg .pred P1;\n\t"                                               \
            "WAIT_LOOP_%=:\n\t"                                                              \
            "mbarrier.try_wait.parity.acquire.cta.shared::cta.b64 P1, [%0], %1, 0x989680;\n\t" \
            "@P1 bra.uni WAIT_DONE_%=;\n\t"                                                  \
            "bra.uni WAIT_LOOP_%=;\n\t"                                                      \
            "WAIT_DONE_%=:\n\t}"                                                             \
            :: "r"(_mbar), "r"(_parity) : "memory");                                         \
    }                                                                                        \
} while (0)

__device__ __forceinline__ void ldsm4(uint32_t r[4], uint32_t addr) {
    asm volatile("ldmatrix.sync.aligned.m8n8.x4.shared.b16 {%0,%1,%2,%3}, [%4];\n"
                 : "=r"(r[0]), "=r"(r[1]), "=r"(r[2]), "=r"(r[3]) : "r"(addr));
}
__device__ __forceinline__ void mma_tf32(float c[4], const uint32_t a[4], const uint32_t b[2]) {
    asm volatile(
        "mma.sync.aligned.m16n8k8.row.col.f32.tf32.tf32.f32 "
        "{%0,%1,%2,%3}, {%4,%5,%6,%7}, {%8,%9}, {%0,%1,%2,%3};\n"
        : "+f"(c[0]), "+f"(c[1]), "+f"(c[2]), "+f"(c[3])
        : "r"(a[0]), "r"(a[1]), "r"(a[2]), "r"(a[3]), "r"(b[0]), "r"(b[1]));
}
__device__ __forceinline__ float tf32r(float f) {
    uint32_t u;
    asm("cvt.rna.tf32.f32 %0, %1;" : "=r"(u) : "f"(f));
    return __uint_as_float(u);
}
// in-register tf32 rounding of a raw fp32 fragment register
__device__ __forceinline__ void tf32q4(uint32_t r[4]) {
#pragma unroll
    for (int i = 0; i < 4; i++) {
        uint32_t u;
        asm("cvt.rna.tf32.f32 %0, %1;" : "=r"(u) : "f"(__uint_as_float(r[i])));
        r[i] = u;
    }
}

// ---------------- kernel 0: router (zeroes counters) ----------------
__global__ void router_kernel(const float* __restrict__ x,
                              const float* __restrict__ wg,
                              float* __restrict__ out_logits, int T) {
    if (blockIdx.x == 0 && threadIdx.x < NE) g_cnt[threadIdx.x] = 0;
    int warp = (blockIdx.x * blockDim.x + threadIdx.x) >> 5;
    int lane = threadIdx.x & 31;
    if (warp >= T) return;
    const float4* xr = (const float4*)(x + (size_t)warp * HD);

    float acc[NE];
#pragma unroll
    for (int e = 0; e < NE; e++) acc[e] = 0.f;
    for (int h = lane; h < HD / 4; h += 32) {
        float4 xv = xr[h];
#pragma unroll
        for (int e = 0; e < NE; e++) {
            float4 wv = ((const float4*)(wg + e * HD))[h];
            acc[e] = fmaf(xv.x, wv.x, fmaf(xv.y, wv.y, fmaf(xv.z, wv.z, fmaf(xv.w, wv.w, acc[e]))));
        }
    }
#pragma unroll
    for (int e = 0; e < NE; e++) {
#pragma unroll
        for (int o = 16; o > 0; o >>= 1)
            acc[e] += __shfl_xor_sync(0xffffffffu, acc[e], o);
    }
    if (out_logits && lane < NE)
        out_logits[(size_t)warp * NE + lane] = acc[lane];
    if (lane == 0) {
        int i0 = 0; float v0 = acc[0];
#pragma unroll
        for (int e = 1; e < NE; e++) if (acc[e] > v0) { v0 = acc[e]; i0 = e; }
        int i1 = -1; float v1 = -1e30f;
#pragma unroll
        for (int e = 0; e < NE; e++) if (e != i0 && acc[e] > v1) { v1 = acc[e]; i1 = e; }
        float e1 = expf(v1 - v0);
        float w0 = 1.f / (1.f + e1);
        float w1 = e1 * w0;
        int p0 = atomicAdd(&g_cnt[i0], 1);
        g_wt[i0][p0] = w0;
        int p1 = atomicAdd(&g_cnt[i1], 1);
        g_wt[i1][p1] = w1;
        g_slot[warp] = make_int4(i0, p0, i1, p1);
    }
}

__global__ void offsets_kernel() {
    if (threadIdx.x == 0) {
        int s = 0;
        for (int e = 0; e < NE; e++) { g_off[e] = s; s += g_cnt[e]; }
        g_off[NE] = s;
    }
}

// ---------------- kernel 2: gather x into slot order + tf32 round ----------------
__global__ void gather_x_kernel(const float* __restrict__ x, int T) {
    int b = blockIdx.x;
    int t = b >> 1, sl = b & 1;
    if (t >= T) return;
    int4 s = g_slot[t];
    int e   = sl ? s.z : s.x;
    int pos = sl ? s.w : s.y;
    size_t row = (size_t)(g_off[e] + pos);
    const float4* src = (const float4*)(x + (size_t)t * HD);
    float4* dst = (float4*)(g_xg + row * HD);
    for (int i = threadIdx.x; i < HD / 4; i += blockDim.x) {
        float4 f = src[i];
        float4 o;
        o.x = tf32r(f.x); o.y = tf32r(f.y); o.z = tf32r(f.z); o.w = tf32r(f.w);
        dst[i] = o;
    }
}

// ================= kernel 3: FC GEMM + fused GLU -> g_hr =================
// B loaded raw from input weights; fragments tf32-rounded in-register.
__global__ void __launch_bounds__(256, 2) fc_mma_kernel(
    const __grid_constant__ CUtensorMap tmA,
    const __grid_constant__ CUtensorMap tmB)
{
    extern __shared__ char sm[];
    __shared__ __align__(8) uint64_t mbars[NST];
    int e = blockIdx.z, cnt = g_cnt[e];
    int m0 = blockIdx.y * A_ROWS;
    if (m0 >= cnt) return;
    int n0 = blockIdx.x * 64;
    int tid = threadIdx.x;
    uint32_t base = (smem_u32(sm) + 1023u) & ~1023u;
    uint32_t mb = smem_u32(mbars);
    int roff = g_off[e];
    int yA = roff + m0;
    int yBa = e * 2048 + n0;
    int yBb = e * 2048 + 1024 + n0;

    int wid = tid >> 5, lane = tid & 31;
    int wm = (wid & 1) * 64, wn = (wid >> 1) * 16;
    uint32_t sw = (uint32_t)(lane & 7);
    uint32_t aBase = base + (uint32_t)(wm + (lane & 15)) * 128;
    uint32_t hA = (lane >> 4) & 1;
    uint32_t bRow = (uint32_t)(wn + (lane & 7) + 8 * ((lane >> 4) & 1)) * 128;
    uint32_t baBase = base + A_TILE + bRow;
    uint32_t bbBase = base + A_TILE + 8192 + bRow;
    uint32_t hB = (lane >> 3) & 1;

    if (tid == 0) {
#pragma unroll
        for (int s = 0; s < NST; s++) MBARRIER_INIT(mb + 8 * s, 1);
        FENCE_PROXY();
    }
    __syncthreads();

    if (tid == 0) {
#pragma unroll
        for (int s = 0; s < 2; s++) {
            MBARRIER_EXPECT_TX(mb + 8 * s, STG_TX);
            tma2d(base + s * STG_B,                  &tmA, s * KC, yA,  mb + 8 * s);
            tma2d(base + s * STG_B + A_TILE,         &tmB, s * KC, yBa, mb + 8 * s);
            tma2d(base + s * STG_B + A_TILE + 8192,  &tmB, s * KC, yBb, mb + 8 * s);
        }
    }

    float accA[4][2][4], accB[4][2][4];
#pragma unroll
    for (int mt = 0; mt < 4; mt++)
#pragma unroll
        for (int nt = 0; nt < 2; nt++)
#pragma unroll
            for (int k = 0; k < 4; k++) { accA[mt][nt][k] = 0.f; accB[mt][nt][k] = 0.f; }

    const int NK = HD / KC;
    for (int kc = 0; kc < NK; kc++) {
        int s = kc % NST;
        MBARRIER_WAIT_PARITY(mb + 8 * s, (kc / NST) & 1);
        int kn = kc + 2;
        if (wid == 0 && kn < NK) {
            if (kc >= 1) BAR_SYNC(1 + (kc - 1) % NST);
            if (tid == 0) {
                int sn = kn % NST;
                MBARRIER_EXPECT_TX(mb + 8 * sn, STG_TX);
                tma2d(base + sn * STG_B,                 &tmA, kn * KC, yA,  mb + 8 * sn);
                tma2d(base + sn * STG_B + A_TILE,        &tmB, kn * KC, yBa, mb + 8 * sn);
                tma2d(base + sn * STG_B + A_TILE + 8192, &tmB, kn * KC, yBb, mb + 8 * sn);
            }
        }
        uint32_t st = (uint32_t)s * STG_B;
#pragma unroll
        for (int ks = 0; ks < 4; ks++) {
            uint32_t ca = ((2u * ks + hA) ^ sw) << 4;
            uint32_t cb = ((2u * ks + hB) ^ sw) << 4;
            uint32_t bfa[4], bfb[4];
            uint32_t af[4][4];
            ldsm4(bfa, baBase + st + cb);
            ldsm4(bfb, bbBase + st + cb);
#pragma unroll
            for (int mt = 0; mt < 4; mt++)
                ldsm4(af[mt], aBase + st + mt * (16 * 128) + ca);
            tf32q4(bfa);
            tf32q4(bfb);
#pragma unroll
            for (int mt = 0; mt < 4; mt++)
#pragma unroll
                for (int nt = 0; nt < 2; nt++) {
                    mma_tf32(accA[mt][nt], af[mt], bfa + 2 * nt);
                    mma_tf32(accB[mt][nt], af[mt], bfb + 2 * nt);
                }
        }
        if (wid != 0) BAR_ARRIVE(1 + s);
    }

    // fused GLU epilogue
    int g = lane >> 2, t = lane & 3;
#pragma unroll
    for (int mt = 0; mt < 4; mt++) {
#pragma unroll
        for (int half = 0; half < 2; half++) {
            int r = wm + mt * 16 + g + half * 8;
            int gi = m0 + r;
            if (gi < cnt) {
                float* orow = g_hr + (size_t)(roff + gi) * ID + n0 + wn;
#pragma unroll
                for (int nt = 0; nt < 2; nt++) {
                    float a0 = accA[mt][nt][half * 2],     b0 = accB[mt][nt][half * 2];
                    float a1 = accA[mt][nt][half * 2 + 1], b1 = accB[mt][nt][half * 2 + 1];
                    float g0 = tf32r(a0 / (1.f + expf(-a0)) * b0);
                    float g1 = tf32r(a1 / (1.f + expf(-a1)) * b1);
                    *(float2*)(orow + nt * 8 + t * 2) = make_float2(g0, g1);
                }
            }
        }
    }
}

// ================= kernel 5: proj GEMM -> g_fc =================
__global__ void __launch_bounds__(256, 2) proj_mma_kernel(
    const __grid_constant__ CUtensorMap tmA,
    const __grid_constant__ CUtensorMap tmB)
{
    extern __shared__ char sm[];
    __shared__ __align__(8) uint64_t mbars[NST];
    int e = blockIdx.z, cnt = g_cnt[e];
    int m0 = blockIdx.y * A_ROWS;
    if (m0 >= cnt) return;
    int n0 = blockIdx.x * 128;
    int tid = threadIdx.x;
    uint32_t base = (smem_u32(sm) + 1023u) & ~1023u;
    uint32_t mb = smem_u32(mbars);
    int roff = g_off[e];
    int yA = roff + m0;
    int yB = e * HD + n0;

    int wid = tid >> 5, lane = tid & 31;
    int wm = (wid & 1) * 64, wn = (wid >> 1) * 32;
    uint32_t sw = (uint32_t)(lane & 7);
    uint32_t aBase = base + (uint32_t)(wm + (lane & 15)) * 128;
    uint32_t hA = (lane >> 4) & 1;
    uint32_t bBase = base + A_TILE + (uint32_t)(wn + (lane & 7) + 8 * ((lane >> 4) & 1)) * 128;
    uint32_t hB = (lane >> 3) & 1;

    if (tid == 0) {
#pragma unroll
        for (int s = 0; s < NST; s++) MBARRIER_INIT(mb + 8 * s, 1);
        FENCE_PROXY();
    }
    __syncthreads();

    if (tid == 0) {
#pragma unroll
        for (int s = 0; s < 2; s++) {
            MBARRIER_EXPECT_TX(mb + 8 * s, STG_TX);
            tma2d(base + s * STG_B,          &tmA, s * KC, yA, mb + 8 * s);
            tma2d(base + s * STG_B + A_TILE, &tmB, s * KC, yB, mb + 8 * s);
        }
    }

    float acc[4][4][4];
#pragma unroll
    for (int mt = 0; mt < 4; mt++)
#pragma unroll
        for (int nt = 0; nt < 4; nt++)
#pragma unroll
            for (int k = 0; k < 4; k++) acc[mt][nt][k] = 0.f;

    const int NK = ID / KC;
    for (int kc = 0; kc < NK; kc++) {
        int s = kc % NST;
        MBARRIER_WAIT_PARITY(mb + 8 * s, (kc / NST) & 1);
        int kn = kc + 2;
        if (wid == 0 && kn < NK) {
            if (kc >= 1) BAR_SYNC(1 + (kc - 1) % NST);
            if (tid == 0) {
                int sn = kn % NST;
                MBARRIER_EXPECT_TX(mb + 8 * sn, STG_TX);
                tma2d(base + sn * STG_B,          &tmA, kn * KC, yA, mb + 8 * sn);
                tma2d(base + sn * STG_B + A_TILE, &tmB, kn * KC, yB, mb + 8 * sn);
            }
        }
        uint32_t st = (uint32_t)s * STG_B;
#pragma unroll
        for (int ks = 0; ks < 4; ks++) {
            uint32_t ca = ((2u * ks + hA) ^ sw) << 4;
            uint32_t cb = ((2u * ks + hB) ^ sw) << 4;
            uint32_t bf[8];
            uint32_t af[4][4];
            ldsm4(bf,     bBase + st + cb);
            ldsm4(bf + 4, bBase + st + 16 * 128 + cb);
#pragma unroll
            for (int mt = 0; mt < 4; mt++)
                ldsm4(af[mt], aBase + st + mt * (16 * 128) + ca);
            tf32q4(bf);
            tf32q4(bf + 4);
#pragma unroll
            for (int mt = 0; mt < 4; mt++)
#pragma unroll
                for (int nt = 0; nt < 4; nt++)
                    mma_tf32(acc[mt][nt], af[mt], bf + 2 * nt);
        }
        if (wid != 0) BAR_ARRIVE(1 + s);
    }

    int g = lane >> 2, t = lane & 3;
#pragma unroll
    for (int mt = 0; mt < 4; mt++) {
#pragma unroll
        for (int half = 0; half < 2; half++) {
            int r = wm + mt * 16 + g + half * 8;
            int gi = m0 + r;
            if (gi < cnt) {
                float* orow = g_fc + (size_t)(roff + gi) * 2048 + n0 + wn;
#pragma unroll
                for (int nt = 0; nt < 4; nt++) {
                    float2 v = half ? make_float2(acc[mt][nt][2], acc[mt][nt][3])
                                    : make_float2(acc[mt][nt][0], acc[mt][nt][1]);
                    *(float2*)(orow + nt * 8 + t * 2) = v;
                }
            }
        }
    }
}

// ---------------- kernel 6: combine ----------------
__global__ void combine_kernel(float* __restrict__ out_y, int T) {
    int idx = blockIdx.x * blockDim.x + threadIdx.x;
    int t = idx >> 9;
    if (t >= T) return;
    int c = (idx & 511) * 4;
    int4 s = g_slot[t];
    int r0 = g_off[s.x] + s.y;
    int r1 = g_off[s.z] + s.w;
    float w0 = g_wt[s.x][s.y];
    float w1 = g_wt[s.z][s.w];
    float4 p0 = *(const float4*)(g_fc + (size_t)r0 * 2048 + c);
    float4 p1 = *(const float4*)(g_fc + (size_t)r1 * 2048 + c);
    float4 v;
    v.x = w0 * p0.x + w1 * p1.x;
    v.y = w0 * p0.y + w1 * p1.y;
    v.z = w0 * p0.z + w1 * p1.z;
    v.w = w0 * p0.w + w1 * p1.w;
    *(float4*)(out_y + (size_t)t * HD + c) = v;
}

// ---------------- host: tensor-map construction ----------------
typedef CUresult (CUDAAPI *EncodeTiled_t)(
    CUtensorMap*, CUtensorMapDataType, cuuint32_t, void*,
    const cuuint64_t*, const cuuint64_t*, const cuuint32_t*, const cuuint32_t*,
    CUtensorMapInterleave, CUtensorMapSwizzle, CUtensorMapL2promotion, CUtensorMapFloatOOBfill);

static void make_map2d(EncodeTiled_t enc, CUtensorMap* m, void* ptr,
                       unsigned long long W, unsigned long long H, unsigned boxH) {
    cuuint64_t dims[2]    = {W, H};
    cuuint64_t strides[1] = {W * 4};
    cuuint32_t box[2]     = {KC, boxH};
    cuuint32_t es[2]      = {1, 1};
    enc(m, CU_TENSOR_MAP_DATA_TYPE_FLOAT32, 2, ptr, dims, strides, box, es,
        CU_TENSOR_MAP_INTERLEAVE_NONE, CU_TENSOR_MAP_SWIZZLE_128B,
        CU_TENSOR_MAP_L2_PROMOTION_L2_128B, CU_TENSOR_MAP_FLOAT_OOB_FILL_NONE);
}

// ---------------- launch ----------------
extern "C" void kernel_launch(void* const* d_in, const int* in_sizes, int n_in,
                              void* d_out, int out_size) {
    const float* x   = (const float*)d_in[0];
    const float* wg  = (const float*)d_in[1];
    const float* wfc = (const float*)d_in[2];
    const float* wp  = (const float*)d_in[3];
    float* out = (float*)d_out;

    int T = in_sizes[0] / HD;
    if (T > TMAX) T = TMAX;

    float* out_y = out;
    long long need = (long long)T * HD + (long long)T * NE;
    float* out_logits = ((long long)out_size >= need) ? out + (size_t)T * HD : nullptr;

    void* fp = nullptr;
    cudaDriverEntryPointQueryResult qr;
    cudaGetDriverEntryPoint("cuTensorMapEncodeTiled", &fp, cudaEnableDefault, &qr);
    EncodeTiled_t enc = (EncodeTiled_t)fp;

    void *p_xg, *p_hr;
    cudaGetSymbolAddress(&p_xg, g_xg);
    cudaGetSymbolAddress(&p_hr, g_hr);

    CUtensorMap tmXA, tmFB, tmHA, tmPB;
    make_map2d(enc, &tmXA, p_xg,        HD, RMAX, 128);        // FC A: gathered x
    make_map2d(enc, &tmFB, (void*)wfc,  HD, NE * 2 * ID, 64);  // FC B: raw w_fc
    make_map2d(enc, &tmHA, p_hr,        ID, RMAX, 128);        // proj A: GLU out
    make_map2d(enc, &tmPB, (void*)wp,   ID, NE * HD, 128);     // proj B: raw w_proj

    cudaFuncSetAttribute(fc_mma_kernel,   cudaFuncAttributeMaxDynamicSharedMemorySize, DSMEM);
    cudaFuncSetAttribute(proj_mma_kernel, cudaFuncAttributeMaxDynamicSharedMemorySize, DSMEM);

    router_kernel<<<(T * 32 + 255) / 256, 256>>>(x, wg, out_logits, T);
    offsets_kernel<<<1, 32>>>();
    gather_x_kernel<<<2 * T, 256>>>(x, T);

    dim3 g1(ID / 64, TMAX / A_ROWS, NE);    // (16, 64, 8)
    fc_mma_kernel<<<g1, 256, DSMEM>>>(tmXA, tmFB);

    dim3 g2(HD / 128, TMAX / A_ROWS, NE);   // (16, 64, 8)
    proj_mma_kernel<<<g2, 256, DSMEM>>>(tmHA, tmPB);

    int ncmb = T * (HD / 4);
    combine_kernel<<<(ncmb + 255) / 256, 256>>>(out_y, T);
}

// round 17
// speedup vs baseline: 1.0130x; 1.0130x over previous
#include <cuda_runtime.h>
#include <cuda.h>
#include <math.h>
#include <stdint.h>

#define NE   8
#define HD   2048
#define ID   1024
#define TMAX 8192
#define RMAX (2*TMAX)

#define KC      32                    // K fp32 elems per chunk (128 bytes/row)
#define NST     3
#define A_ROWS  128
#define A_TILE  (A_ROWS*128)          // 16384 bytes
#define STG_B   (2*A_TILE)            // 32768 (A + B)
#define STG_TX  32768
#define DSMEM   (NST*STG_B + 1024)    // 99328 -> 2 CTAs/SM

// ---------------- persistent device scratch ----------------
__device__ int   g_cnt[NE];
__device__ int   g_off[NE + 1];
__device__ float g_wt[NE][TMAX];
__device__ int4  g_slot[TMAX];
__device__ __align__(256) float g_xg[(size_t)RMAX * HD];          // gathered tf32 x (slot order)
__device__ __align__(256) float g_fcr[(size_t)NE * 2 * ID * HD];  // tf32-rounded w_fc
__device__ __align__(256) float g_wpr[(size_t)NE * HD * ID];      // tf32-rounded w_proj
__device__ __align__(256) float g_hr[(size_t)RMAX * ID];          // GLU out (tf32-rounded)
__device__ __align__(256) float g_fc[(size_t)RMAX * 2048];        // proj out

// ---------------- PTX helpers ----------------
__device__ __forceinline__ uint32_t smem_u32(const void* p) {
    uint32_t a;
    asm("{ .reg .u64 t; cvta.to.shared.u64 t, %1; cvt.u32.u64 %0, t; }" : "=r"(a) : "l"(p));
    return a;
}
__device__ __forceinline__ void tma2d(uint32_t dst, const CUtensorMap* tm,
                                      int cx, int cy, uint32_t mbar) {
    asm volatile(
        "cp.async.bulk.tensor.2d.shared::cta.global.tile.mbarrier::complete_tx::bytes "
        "[%0], [%1, {%2, %3}], [%4];"
        :: "r"(dst), "l"(tm), "r"(cx), "r"(cy), "r"(mbar) : "memory");
}
#define MBARRIER_INIT(mbar, cnt) \
    asm volatile("mbarrier.init.shared.b64 [%0], %1;" :: "r"((uint32_t)(mbar)), "r"((uint32_t)(cnt)) : "memory")
#define MBARRIER_EXPECT_TX(mbar, tx) \
    asm volatile("mbarrier.arrive.expect_tx.shared.b64 _, [%0], %1;" :: "r"((uint32_t)(mbar)), "r"((uint32_t)(tx)) : "memory")
#define FENCE_PROXY() asm volatile("fence.proxy.async.shared::cta;" ::: "memory")
#define BAR_SYNC(id)   asm volatile("bar.sync %0, 256;"   :: "r"(id) : "memory")
#define BAR_ARRIVE(id) asm volatile("bar.arrive %0, 256;" :: "r"(id) : "memory")

#define MBARRIER_WAIT_PARITY(mbar_addr, phase_parity) do {                                   \
    uint32_t _mbar = (uint32_t)(mbar_addr);                                                  \
    uint32_t _parity = (uint32_t)(phase_parity);                                             \
    uint32_t _done;                                                                          \
    asm volatile("{\n\t.reg .pred p;\n\t"                                                    \
        "mbarrier.try_wait.parity.acquire.cta.shared::cta.b64 p, [%1], %2;\n\t"              \
        "selp.b32 %0, 1, 0, p;\n\t}"                                                         \
        : "=r"(_done) : "r"(_mbar), "r"(_parity) : "memory");                                \
    if (!_done) {                                                                            \
        asm volatile("{\n\t.reg .pred P1;\n\t"                                               \
            "WAIT_LOOP_%=:\n\t"                                                              \
            "mbarrier.try_wait.parity.acquire.cta.shared::cta.b64 P1, [%0], %1, 0x989680;\n\t" \
            "@P1 bra.uni WAIT_DONE_%=;\n\t"                                                  \
            "bra.uni WAIT_LOOP_%=;\n\t"                                                      \
            "WAIT_DONE_%=:\n\t}"                                                             \
            :: "r"(_mbar), "r"(_parity) : "memory");                                         \
    }                                                                                        \
} while (0)

__device__ __forceinline__ void ldsm4(uint32_t r[4], uint32_t addr) {
    asm volatile("ldmatrix.sync.aligned.m8n8.x4.shared.b16 {%0,%1,%2,%3}, [%4];\n"
                 : "=r"(r[0]), "=r"(r[1]), "=r"(r[2]), "=r"(r[3]) : "r"(addr));
}
__device__ __forceinline__ void mma_tf32(float c[4], const uint32_t a[4], const uint32_t b[2]) {
    asm volatile(
        "mma.sync.aligned.m16n8k8.row.col.f32.tf32.tf32.f32 "
        "{%0,%1,%2,%3}, {%4,%5,%6,%7}, {%8,%9}, {%0,%1,%2,%3};\n"
        : "+f"(c[0]), "+f"(c[1]), "+f"(c[2]), "+f"(c[3])
        : "r"(a[0]), "r"(a[1]), "r"(a[2]), "r"(a[3]), "r"(b[0]), "r"(b[1]));
}
__device__ __forceinline__ float tf32r(float f) {
    uint32_t u;
    asm("cvt.rna.tf32.f32 %0, %1;" : "=r"(u) : "f"(f));
    return __uint_as_float(u);
}

// ---------------- sizes for fused prep ----------------
#define WFC4 ((size_t)NE * 2 * ID * HD / 4)
#define WP4  ((size_t)NE * HD * ID / 4)
#define NWFCB ((unsigned)((WFC4 + 255) / 256))
#define NWPB  ((unsigned)((WP4 + 255) / 256))

__device__ __forceinline__ void round4(const float* src, float* dst, size_t i) {
    float4 f = *(const float4*)(src + i * 4);
    float4 o;
    o.x = tf32r(f.x); o.y = tf32r(f.y); o.z = tf32r(f.z); o.w = tf32r(f.w);
    *(float4*)(dst + i * 4) = o;
}

// ---------------- kernel 1: w_fc rounding ∥ router ----------------
__global__ void router_wfc_kernel(const float* __restrict__ wfc,
                                  const float* __restrict__ x,
                                  const float* __restrict__ wg,
                                  float* __restrict__ out_logits, int T) {
    if (blockIdx.x == 0 && threadIdx.x < NE) g_cnt[threadIdx.x] = 0;
    if (blockIdx.x < NWFCB) {
        size_t i = (size_t)blockIdx.x * blockDim.x + threadIdx.x;
        if (i < WFC4) round4(wfc, g_fcr, i);
        return;
    }
    int warp = (int)(((blockIdx.x - NWFCB) * blockDim.x + threadIdx.x) >> 5);
    int lane = threadIdx.x & 31;
    if (warp >= T) return;
    const float4* xr = (const float4*)(x + (size_t)warp * HD);

    float acc[NE];
#pragma unroll
    for (int e = 0; e < NE; e++) acc[e] = 0.f;
    for (int h = lane; h < HD / 4; h += 32) {
        float4 xv = xr[h];
#pragma unroll
        for (int e = 0; e < NE; e++) {
            float4 wv = ((const float4*)(wg + e * HD))[h];
            acc[e] = fmaf(xv.x, wv.x, fmaf(xv.y, wv.y, fmaf(xv.z, wv.z, fmaf(xv.w, wv.w, acc[e]))));
        }
    }
#pragma unroll
    for (int e = 0; e < NE; e++) {
#pragma unroll
        for (int o = 16; o > 0; o >>= 1)
            acc[e] += __shfl_xor_sync(0xffffffffu, acc[e], o);
    }
    if (out_logits && lane < NE)
        out_logits[(size_t)warp * NE + lane] = acc[lane];
    if (lane == 0) {
        int i0 = 0; float v0 = acc[0];
#pragma unroll
        for (int e = 1; e < NE; e++) if (acc[e] > v0) { v0 = acc[e]; i0 = e; }
        int i1 = -1; float v1 = -1e30f;
#pragma unroll
        for (int e = 0; e < NE; e++) if (e != i0 && acc[e] > v1) { v1 = acc[e]; i1 = e; }
        float e1 = expf(v1 - v0);
        float w0 = 1.f / (1.f + e1);
        float w1 = e1 * w0;
        int p0 = atomicAdd(&g_cnt[i0], 1);
        g_wt[i0][p0] = w0;
        int p1 = atomicAdd(&g_cnt[i1], 1);
        g_wt[i1][p1] = w1;
        g_slot[warp] = make_int4(i0, p0, i1, p1);
    }
}

__global__ void offsets_kernel() {
    if (threadIdx.x == 0) {
        int s = 0;
        for (int e = 0; e < NE; e++) { g_off[e] = s; s += g_cnt[e]; }
        g_off[NE] = s;
    }
}

// ---------------- kernel 2: gather x (slot order, tf32) ∥ w_proj rounding ----------------
__global__ void gather_wp_kernel(const float* __restrict__ x,
                                 const float* __restrict__ wp, int T) {
    unsigned b = blockIdx.x;
    if (b < (unsigned)(2 * T)) {
        int t = b >> 1, sl = b & 1;
        int4 s = g_slot[t];
        int e   = sl ? s.z : s.x;
        int pos = sl ? s.w : s.y;
        size_t row = (size_t)(g_off[e] + pos);
        const float4* src = (const float4*)(x + (size_t)t * HD);
        float4* dst = (float4*)(g_xg + row * HD);
        for (int i = threadIdx.x; i < HD / 4; i += blockDim.x) {
            float4 f = src[i];
            float4 o;
            o.x = tf32r(f.x); o.y = tf32r(f.y); o.z = tf32r(f.z); o.w = tf32r(f.w);
            dst[i] = o;
        }
    } else {
        size_t i = (size_t)(b - 2 * T) * blockDim.x + threadIdx.x;
        if (i < WP4) round4(wp, g_wpr, i);
    }
}

// ================= kernel 3: FC GEMM + fused GLU -> g_hr =================
// Named-barrier producer/consumer split (R15-validated).
__global__ void __launch_bounds__(256, 2) fc_mma_kernel(
    const __grid_constant__ CUtensorMap tmA,
    const __grid_constant__ CUtensorMap tmB)
{
    extern __shared__ char sm[];
    __shared__ __align__(8) uint64_t mbars[NST];
    int e = blockIdx.z, cnt = g_cnt[e];
    int m0 = blockIdx.y * A_ROWS;
    if (m0 >= cnt) return;
    int n0 = blockIdx.x * 64;
    int tid = threadIdx.x;
    uint32_t base = (smem_u32(sm) + 1023u) & ~1023u;
    uint32_t mb = smem_u32(mbars);
    int roff = g_off[e];
    int yA = roff + m0;
    int yBa = e * 2048 + n0;
    int yBb = e * 2048 + 1024 + n0;

    int wid = tid >> 5, lane = tid & 31;
    int wm = (wid & 1) * 64, wn = (wid >> 1) * 16;
    uint32_t sw = (uint32_t)(lane & 7);
    uint32_t aBase = base + (uint32_t)(wm + (lane & 15)) * 128;
    uint32_t hA = (lane >> 4) & 1;
    uint32_t bRow = (uint32_t)(wn + (lane & 7) + 8 * ((lane >> 4) & 1)) * 128;
    uint32_t baBase = base + A_TILE + bRow;
    uint32_t bbBase = base + A_TILE + 8192 + bRow;
    uint32_t hB = (lane >> 3) & 1;

    if (tid == 0) {
#pragma unroll
        for (int s = 0; s < NST; s++) MBARRIER_INIT(mb + 8 * s, 1);
        FENCE_PROXY();
    }
    __syncthreads();

    if (tid == 0) {
#pragma unroll
        for (int s = 0; s < 2; s++) {
            MBARRIER_EXPECT_TX(mb + 8 * s, STG_TX);
            tma2d(base + s * STG_B,                  &tmA, s * KC, yA,  mb + 8 * s);
            tma2d(base + s * STG_B + A_TILE,         &tmB, s * KC, yBa, mb + 8 * s);
            tma2d(base + s * STG_B + A_TILE + 8192,  &tmB, s * KC, yBb, mb + 8 * s);
        }
    }

    float accA[4][2][4], accB[4][2][4];
#pragma unroll
    for (int mt = 0; mt < 4; mt++)
#pragma unroll
        for (int nt = 0; nt < 2; nt++)
#pragma unroll
            for (int k = 0; k < 4; k++) { accA[mt][nt][k] = 0.f; accB[mt][nt][k] = 0.f; }

    const int NK = HD / KC;
    for (int kc = 0; kc < NK; kc++) {
        int s = kc % NST;
        MBARRIER_WAIT_PARITY(mb + 8 * s, (kc / NST) & 1);
        int kn = kc + 2;
        if (wid == 0 && kn < NK) {
            if (kc >= 1) BAR_SYNC(1 + (kc - 1) % NST);
            if (tid == 0) {
                int sn = kn % NST;
                MBARRIER_EXPECT_TX(mb + 8 * sn, STG_TX);
                tma2d(base + sn * STG_B,                 &tmA, kn * KC, yA,  mb + 8 * sn);
                tma2d(base + sn * STG_B + A_TILE,        &tmB, kn * KC, yBa, mb + 8 * sn);
                tma2d(base + sn * STG_B + A_TILE + 8192, &tmB, kn * KC, yBb, mb + 8 * sn);
            }
        }
        uint32_t st = (uint32_t)s * STG_B;
#pragma unroll
        for (int ks = 0; ks < 4; ks++) {
            uint32_t ca = ((2u * ks + hA) ^ sw) << 4;
            uint32_t cb = ((2u * ks + hB) ^ sw) << 4;
            uint32_t bfa[4], bfb[4];
            uint32_t af[4][4];
            ldsm4(bfa, baBase + st + cb);
            ldsm4(bfb, bbBase + st + cb);
#pragma unroll
            for (int mt = 0; mt < 4; mt++)
                ldsm4(af[mt], aBase + st + mt * (16 * 128) + ca);
#pragma unroll
            for (int mt = 0; mt < 4; mt++)
#pragma unroll
                for (int nt = 0; nt < 2; nt++) {
                    mma_tf32(accA[mt][nt], af[mt], bfa + 2 * nt);
                    mma_tf32(accB[mt][nt], af[mt], bfb + 2 * nt);
                }
        }
        if (wid != 0) BAR_ARRIVE(1 + s);
    }

    int g = lane >> 2, t = lane & 3;
#pragma unroll
    for (int mt = 0; mt < 4; mt++) {
#pragma unroll
        for (int half = 0; half < 2; half++) {
            int r = wm + mt * 16 + g + half * 8;
            int gi = m0 + r;
            if (gi < cnt) {
                float* orow = g_hr + (size_t)(roff + gi) * ID + n0 + wn;
#pragma unroll
                for (int nt = 0; nt < 2; nt++) {
                    float a0 = accA[mt][nt][half * 2],     b0 = accB[mt][nt][half * 2];
                    float a1 = accA[mt][nt][half * 2 + 1], b1 = accB[mt][nt][half * 2 + 1];
                    float g0 = tf32r(a0 / (1.f + expf(-a0)) * b0);
                    float g1 = tf32r(a1 / (1.f + expf(-a1)) * b1);
                    *(float2*)(orow + nt * 8 + t * 2) = make_float2(g0, g1);
                }
            }
        }
    }
}

// ================= kernel 5: proj GEMM -> g_fc =================
__global__ void __launch_bounds__(256, 2) proj_mma_kernel(
    const __grid_constant__ CUtensorMap tmA,
    const __grid_constant__ CUtensorMap tmB)
{
    extern __shared__ char sm[];
    __shared__ __align__(8) uint64_t mbars[NST];
    int e = blockIdx.z, cnt = g_cnt[e];
    int m0 = blockIdx.y * A_ROWS;
    if (m0 >= cnt) return;
    int n0 = blockIdx.x * 128;
    int tid = threadIdx.x;
    uint32_t base = (smem_u32(sm) + 1023u) & ~1023u;
    uint32_t mb = smem_u32(mbars);
    int roff = g_off[e];
    int yA = roff + m0;
    int yB = e * HD + n0;

    int wid = tid >> 5, lane = tid & 31;
    int wm = (wid & 1) * 64, wn = (wid >> 1) * 32;
    uint32_t sw = (uint32_t)(lane & 7);
    uint32_t aBase = base + (uint32_t)(wm + (lane & 15)) * 128;
    uint32_t hA = (lane >> 4) & 1;
    uint32_t bBase = base + A_TILE + (uint32_t)(wn + (lane & 7) + 8 * ((lane >> 4) & 1)) * 128;
    uint32_t hB = (lane >> 3) & 1;

    if (tid == 0) {
#pragma unroll
        for (int s = 0; s < NST; s++) MBARRIER_INIT(mb + 8 * s, 1);
        FENCE_PROXY();
    }
    __syncthreads();

    if (tid == 0) {
#pragma unroll
        for (int s = 0; s < 2; s++) {
            MBARRIER_EXPECT_TX(mb + 8 * s, STG_TX);
            tma2d(base + s * STG_B,          &tmA, s * KC, yA, mb + 8 * s);
            tma2d(base + s * STG_B + A_TILE, &tmB, s * KC, yB, mb + 8 * s);
        }
    }

    float acc[4][4][4];
#pragma unroll
    for (int mt = 0; mt < 4; mt++)
#pragma unroll
        for (int nt = 0; nt < 4; nt++)
#pragma unroll
            for (int k = 0; k < 4; k++) acc[mt][nt][k] = 0.f;

    const int NK = ID / KC;
    for (int kc = 0; kc < NK; kc++) {
        int s = kc % NST;
        MBARRIER_WAIT_PARITY(mb + 8 * s, (kc / NST) & 1);
        int kn = kc + 2;
        if (wid == 0 && kn < NK) {
            if (kc >= 1) BAR_SYNC(1 + (kc - 1) % NST);
            if (tid == 0) {
                int sn = kn % NST;
                MBARRIER_EXPECT_TX(mb + 8 * sn, STG_TX);
                tma2d(base + sn * STG_B,          &tmA, kn * KC, yA, mb + 8 * sn);
                tma2d(base + sn * STG_B + A_TILE, &tmB, kn * KC, yB, mb + 8 * sn);
            }
        }
        uint32_t st = (uint32_t)s * STG_B;
#pragma unroll
        for (int ks = 0; ks < 4; ks++) {
            uint32_t ca = ((2u * ks + hA) ^ sw) << 4;
            uint32_t cb = ((2u * ks + hB) ^ sw) << 4;
            uint32_t bf[8];
            uint32_t af[4][4];
            ldsm4(bf,     bBase + st + cb);
            ldsm4(bf + 4, bBase + st + 16 * 128 + cb);
#pragma unroll
            for (int mt = 0; mt < 4; mt++)
                ldsm4(af[mt], aBase + st + mt * (16 * 128) + ca);
#pragma unroll
            for (int mt = 0; mt < 4; mt++)
#pragma unroll
                for (int nt = 0; nt < 4; nt++)
                    mma_tf32(acc[mt][nt], af[mt], bf + 2 * nt);
        }
        if (wid != 0) BAR_ARRIVE(1 + s);
    }

    int g = lane >> 2, t = lane & 3;
#pragma unroll
    for (int mt = 0; mt < 4; mt++) {
#pragma unroll
        for (int half = 0; half < 2; half++) {
            int r = wm + mt * 16 + g + half * 8;
            int gi = m0 + r;
            if (gi < cnt) {
                float* orow = g_fc + (size_t)(roff + gi) * 2048 + n0 + wn;
#pragma unroll
                for (int nt = 0; nt < 4; nt++) {
                    float2 v = half ? make_float2(acc[mt][nt][2], acc[mt][nt][3])
                                    : make_float2(acc[mt][nt][0], acc[mt][nt][1]);
                    *(float2*)(orow + nt * 8 + t * 2) = v;
                }
            }
        }
    }
}

// ---------------- kernel 6: combine ----------------
__global__ void combine_kernel(float* __restrict__ out_y, int T) {
    int idx = blockIdx.x * blockDim.x + threadIdx.x;
    int t = idx >> 9;
    if (t >= T) return;
    int c = (idx & 511) * 4;
    int4 s = g_slot[t];
    int r0 = g_off[s.x] + s.y;
    int r1 = g_off[s.z] + s.w;
    float w0 = g_wt[s.x][s.y];
    float w1 = g_wt[s.z][s.w];
    float4 p0 = *(const float4*)(g_fc + (size_t)r0 * 2048 + c);
    float4 p1 = *(const float4*)(g_fc + (size_t)r1 * 2048 + c);
    float4 v;
    v.x = w0 * p0.x + w1 * p1.x;
    v.y = w0 * p0.y + w1 * p1.y;
    v.z = w0 * p0.z + w1 * p1.z;
    v.w = w0 * p0.w + w1 * p1.w;
    *(float4*)(out_y + (size_t)t * HD + c) = v;
}

// ---------------- host: tensor-map construction ----------------
typedef CUresult (CUDAAPI *EncodeTiled_t)(
    CUtensorMap*, CUtensorMapDataType, cuuint32_t, void*,
    const cuuint64_t*, const cuuint64_t*, const cuuint32_t*, const cuuint32_t*,
    CUtensorMapInterleave, CUtensorMapSwizzle, CUtensorMapL2promotion, CUtensorMapFloatOOBfill);

static void make_map2d(EncodeTiled_t enc, CUtensorMap* m, void* ptr,
                       unsigned long long W, unsigned long long H, unsigned boxH) {
    cuuint64_t dims[2]    = {W, H};
    cuuint64_t strides[1] = {W * 4};
    cuuint32_t box[2]     = {KC, boxH};
    cuuint32_t es[2]      = {1, 1};
    enc(m, CU_TENSOR_MAP_DATA_TYPE_FLOAT32, 2, ptr, dims, strides, box, es,
        CU_TENSOR_MAP_INTERLEAVE_NONE, CU_TENSOR_MAP_SWIZZLE_128B,
        CU_TENSOR_MAP_L2_PROMOTION_L2_128B, CU_TENSOR_MAP_FLOAT_OOB_FILL_NONE);
}

// ---------------- launch ----------------
extern "C" void kernel_launch(void* const* d_in, const int* in_sizes, int n_in,
                              void* d_out, int out_size) {
    const float* x   = (const float*)d_in[0];
    const float* wg  = (const float*)d_in[1];
    const float* wfc = (const float*)d_in[2];
    const float* wp  = (const float*)d_in[3];
    float* out = (float*)d_out;

    int T = in_sizes[0] / HD;
    if (T > TMAX) T = TMAX;

    float* out_y = out;
    long long need = (long long)T * HD + (long long)T * NE;
    float* out_logits = ((long long)out_size >= need) ? out + (size_t)T * HD : nullptr;

    void* fp = nullptr;
    cudaDriverEntryPointQueryResult qr;
    cudaGetDriverEntryPoint("cuTensorMapEncodeTiled", &fp, cudaEnableDefault, &qr);
    EncodeTiled_t enc = (EncodeTiled_t)fp;

    void *p_xg, *p_fcr, *p_wpr, *p_hr;
    cudaGetSymbolAddress(&p_xg,  g_xg);
    cudaGetSymbolAddress(&p_fcr, g_fcr);
    cudaGetSymbolAddress(&p_wpr, g_wpr);
    cudaGetSymbolAddress(&p_hr,  g_hr);

    CUtensorMap tmXA, tmFB, tmHA, tmPB;
    make_map2d(enc, &tmXA, p_xg,  HD, RMAX, 128);
    make_map2d(enc, &tmFB, p_fcr, HD, NE * 2 * ID, 64);
    make_map2d(enc, &tmHA, p_hr,  ID, RMAX, 128);
    make_map2d(enc, &tmPB, p_wpr, ID, NE * HD, 128);

    cudaFuncSetAttribute(fc_mma_kernel,   cudaFuncAttributeMaxDynamicSharedMemorySize, DSMEM);
    cudaFuncSetAttribute(proj_mma_kernel, cudaFuncAttributeMaxDynamicSharedMemorySize, DSMEM);

    unsigned nrb = (unsigned)((T * 32 + 255) / 256);
    router_wfc_kernel<<<NWFCB + nrb, 256>>>(wfc, x, wg, out_logits, T);
    offsets_kernel<<<1, 32>>>();
    gather_wp_kernel<<<(unsigned)(2 * T) + NWPB, 256>>>(x, wp, T);

    dim3 g1(ID / 64, TMAX / A_ROWS, NE);    // (16, 64, 8)
    fc_mma_kernel<<<g1, 256, DSMEM>>>(tmXA, tmFB);

    dim3 g2(HD / 128, TMAX / A_ROWS, NE);   // (16, 64, 8)
    proj_mma_kernel<<<g2, 256, DSMEM>>>(tmHA, tmPB);

    int ncmb = T * (HD / 4);
    combine_kernel<<<(ncmb + 255) / 256, 256>>>(out_y, T);
}